// round 7
// baseline (speedup 1.0000x reference)
#include <cuda_runtime.h>
#include <cuda_fp16.h>
#include <cstdint>
#include <math.h>

// ------------------------------ scratch ------------------------------------
__device__ __half g_xh  [8192 * 1024];
__device__ __half g_Wcat[3 * 1024 * 1024];          // [Wq;Wk;Wv] as [3072,1024]
__device__ __half g_Woh [1024 * 1024];
__device__ float  g_bcat[3072];                     // [bq;bk;bv]
__device__ __half g_QKV [8192LL * 3072];            // per row: [Q|K|V]
__device__ __half g_Sh  [4LL * 2048 * 2048];        // scores -> softmax in place
__device__ __half g_Vth [8192 * 1024];              // V^T per batch [1024,2048]
__device__ __half g_Oh  [8192 * 1024];

// ------------------------------ helpers ------------------------------------
__device__ __forceinline__ uint32_t smem_u32(const void* p) {
    uint32_t a;
    asm("{ .reg .u64 t; cvta.to.shared.u64 t, %1; cvt.u32.u64 %0, t; }"
        : "=r"(a) : "l"(p));
    return a;
}
__device__ __forceinline__ void ldsm4(uint32_t& r0, uint32_t& r1,
                                      uint32_t& r2, uint32_t& r3, uint32_t a) {
    asm volatile("ldmatrix.sync.aligned.m8n8.x4.shared.b16 {%0,%1,%2,%3}, [%4];"
                 : "=r"(r0), "=r"(r1), "=r"(r2), "=r"(r3) : "r"(a));
}
__device__ __forceinline__ void mma_f16(float* d, const uint32_t* a,
                                        const uint32_t* b) {
    asm volatile(
        "mma.sync.aligned.m16n8k16.row.col.f32.f16.f16.f32 "
        "{%0,%1,%2,%3}, {%4,%5,%6,%7}, {%8,%9}, {%0,%1,%2,%3};"
        : "+f"(d[0]), "+f"(d[1]), "+f"(d[2]), "+f"(d[3])
        : "r"(a[0]), "r"(a[1]), "r"(a[2]), "r"(a[3]), "r"(b[0]), "r"(b[1]));
}
#define CP_ASYNC16(s, g) \
    asm volatile("cp.async.cg.shared.global [%0], [%1], 16;" :: "r"(s), "l"(g))
#define CP_COMMIT()  asm volatile("cp.async.commit_group;" ::: "memory")
#define CP_WAIT2()   asm volatile("cp.async.wait_group 2;" ::: "memory")

// ------------------------------ GEMM ---------------------------------------
// C[M,N] = A[M,K] @ B[N,K]^T (half in, fp16 MMA, fp32 acc). Row strides lda/ldb/ldc.
static constexpr int BM = 128, BN = 256, BK = 64, STAGES = 4;
static constexpr int A_BYTES     = BM * BK * 2;            // 16384
static constexpr int B_BYTES     = BN * BK * 2;            // 32768
static constexpr int STAGE_BYTES = A_BYTES + B_BYTES;      // 49152
static constexpr int SMEM_TOTAL  = STAGES * STAGE_BYTES;   // 196608

__device__ __forceinline__ uint32_t swz(int r, int q) {
    return (uint32_t)(r * 128 + ((q ^ (r & 7)) << 4));
}

template <bool BIAS, bool SCALE, bool OUTH>
__global__ __launch_bounds__(256, 1) void tc_gemm(
    const __half* __restrict__ A, const __half* __restrict__ Bm,
    const float* __restrict__ bias, void* __restrict__ Cv,
    int M, int N, int K, int lda, int ldb, int ldc, float scale,
    long long sA, long long sB, long long sC)
{
    extern __shared__ __align__(1024) char smem[];
    const uint32_t sb = smem_u32(smem);

    const int tid  = threadIdx.x;
    const int lane = tid & 31;
    const int wid  = tid >> 5;
    const int wm   = (wid >> 2) * 64;
    const int wn   = (wid & 3) * 64;

    const long long bz = blockIdx.z;
    A  += bz * sA;
    Bm += bz * sB;
    const int m0 = blockIdx.y * BM;
    const int n0 = blockIdx.x * BN;
    const int nchunks = K / BK;

    const int midx = lane >> 3, l7 = lane & 7;
    int aR[4];
#pragma unroll
    for (int mi = 0; mi < 4; mi++) aR[mi] = wm + mi * 16 + ((midx & 1) << 3) + l7;
    const int aKH = midx >> 1;
    int bR[4];
#pragma unroll
    for (int n2 = 0; n2 < 4; n2++) bR[n2] = wn + n2 * 16 + ((midx >> 1) << 3) + l7;
    const int bKH = midx & 1;

    float acc[4][8][4];
#pragma unroll
    for (int mi = 0; mi < 4; mi++)
#pragma unroll
        for (int ni = 0; ni < 8; ni++)
#pragma unroll
            for (int j = 0; j < 4; j++) acc[mi][ni][j] = 0.0f;

    auto issue = [&](int c) {
        if (c < nchunks) {
            const int s = c % STAGES;
            const uint32_t As = sb + s * STAGE_BYTES;
            const uint32_t Bs = As + A_BYTES;
            const int k0 = c * BK;
#pragma unroll
            for (int i = tid; i < 3072; i += 256) {
                if (i < 1024) {
                    const int r = i >> 3, q = i & 7;
                    CP_ASYNC16(As + swz(r, q),
                               A + (long long)(m0 + r) * lda + k0 + q * 8);
                } else {
                    const int idx = i - 1024;
                    const int r = idx >> 3, q = idx & 7;
                    CP_ASYNC16(Bs + swz(r, q),
                               Bm + (long long)(n0 + r) * ldb + k0 + q * 8);
                }
            }
        }
        CP_COMMIT();
    };

    issue(0);
    issue(1);
    issue(2);

    for (int c = 0; c < nchunks; c++) {
        CP_WAIT2();
        __syncthreads();
        issue(c + 3);

        const int s = c % STAGES;
        const uint32_t As = sb + s * STAGE_BYTES;
        const uint32_t Bs = As + A_BYTES;

#pragma unroll
        for (int kk = 0; kk < 4; kk++) {        // 4 x k16
            uint32_t aF[4][4], bF[8][2];
#pragma unroll
            for (int mi = 0; mi < 4; mi++)
                ldsm4(aF[mi][0], aF[mi][1], aF[mi][2], aF[mi][3],
                      As + swz(aR[mi], kk * 2 + aKH));
#pragma unroll
            for (int n2 = 0; n2 < 4; n2++) {
                uint32_t r0, r1, r2, r3;
                ldsm4(r0, r1, r2, r3, Bs + swz(bR[n2], kk * 2 + bKH));
                bF[n2 * 2 + 0][0] = r0;
                bF[n2 * 2 + 0][1] = r1;
                bF[n2 * 2 + 1][0] = r2;
                bF[n2 * 2 + 1][1] = r3;
            }
#pragma unroll
            for (int mi = 0; mi < 4; mi++)
#pragma unroll
                for (int ni = 0; ni < 8; ni++)
                    mma_f16(acc[mi][ni], aF[mi], bF[ni]);
        }
    }

    // ------------------ epilogue ------------------
    const int crow = lane >> 2;
    const int ccol = (lane & 3) * 2;
#pragma unroll
    for (int mi = 0; mi < 4; mi++) {
#pragma unroll
        for (int ni = 0; ni < 8; ni++) {
            const int col = n0 + wn + ni * 8 + ccol;
            float2 b2 = make_float2(0.f, 0.f);
            if (BIAS) b2 = *(const float2*)&bias[col];
#pragma unroll
            for (int h = 0; h < 2; h++) {
                const int row = m0 + wm + mi * 16 + crow + h * 8;
                float vx = acc[mi][ni][h * 2 + 0];
                float vy = acc[mi][ni][h * 2 + 1];
                if (SCALE) { vx *= scale; vy *= scale; }
                if (BIAS)  { vx += b2.x;  vy += b2.y; }
                if (OUTH) {
                    __half2* C = (__half2*)((__half*)Cv + bz * sC);
                    C[((long long)row * ldc + col) >> 1] = __floats2half2_rn(vx, vy);
                } else {
                    float* C = (float*)Cv + bz * sC;
                    *(float2*)&C[(long long)row * ldc + col] = make_float2(vx, vy);
                }
            }
        }
    }
}

// ------------------------------ prep (all conversions in one) --------------
static constexpr long long XG = 8192LL * 1024 / 4;      // float4 groups of x
static constexpr long long WG = 1024LL * 1024 / 4;      // per weight
static constexpr long long PREP_TOTAL = XG + 4 * WG + 768;

__global__ __launch_bounds__(256) void prep(
    const float* __restrict__ x,
    const float* __restrict__ Wq, const float* __restrict__ Wk,
    const float* __restrict__ Wv, const float* __restrict__ Wo,
    const float* __restrict__ bq, const float* __restrict__ bk,
    const float* __restrict__ bv,
    __half* __restrict__ xh, __half* __restrict__ Wcat,
    __half* __restrict__ Woh, float* __restrict__ bcat)
{
    const long long g = (long long)blockIdx.x * 256 + threadIdx.x;
    if (g >= PREP_TOTAL) return;

    const float* s;
    __half* d;
    long long off;
    if (g < XG)              { s = x;  d = xh;             off = g; }
    else if (g < XG + WG)    { s = Wq; d = Wcat;           off = g - XG; }
    else if (g < XG + 2*WG)  { s = Wk; d = Wcat + 1048576; off = g - XG - WG; }
    else if (g < XG + 3*WG)  { s = Wv; d = Wcat + 2097152; off = g - XG - 2*WG; }
    else if (g < XG + 4*WG)  { s = Wo; d = Woh;            off = g - XG - 3*WG; }
    else {
        const long long idx = (g - XG - 4*WG) * 4;      // 0..3068
        const float* bs = (idx < 1024) ? bq + idx
                        : (idx < 2048) ? bk + (idx - 1024)
                                       : bv + (idx - 2048);
        *(float4*)&bcat[idx] = *(const float4*)bs;
        return;
    }
    float4 v = *(const float4*)&s[off * 4];
    *(__half2*)&d[off * 4]     = __floats2half2_rn(v.x, v.y);
    *(__half2*)&d[off * 4 + 2] = __floats2half2_rn(v.z, v.w);
}

// ------------------------------ transpose ----------------------------------
// Vth[b][d][t] = QKV[b*T + t][2048 + d]
__global__ __launch_bounds__(256) void transpose_h(
    const __half* __restrict__ QKV, __half* __restrict__ Vt)
{
    __shared__ __half tile[32][33];
    const long long b = blockIdx.z;
    const __half* src = QKV + b * 2048LL * 3072 + 2048;
    __half* dst = Vt + b * 2048LL * 1024;
    const int x0 = blockIdx.x * 32;   // d
    const int y0 = blockIdx.y * 32;   // t
    const int tx = threadIdx.x & 31;
    const int ty = threadIdx.x >> 5;
#pragma unroll
    for (int i = 0; i < 32; i += 8)
        tile[ty + i][tx] = src[(long long)(y0 + ty + i) * 3072 + x0 + tx];
    __syncthreads();
#pragma unroll
    for (int i = 0; i < 32; i += 8)
        dst[(long long)(x0 + ty + i) * 2048 + y0 + tx] = tile[tx][ty + i];
}

// ------------------------------ softmax (half, in place, per batch) --------
__global__ __launch_bounds__(256) void softmax_h(__half* __restrict__ S, int T)
{
    __shared__ float red[256];
    const long long row = blockIdx.x;
    __half* r = S + row * T;
    const int t = threadIdx.x;
    const int i = t * 8;                       // 8 halves per thread, T=2048

    uint4 u = *(const uint4*)&r[i];
    float v[8];
    {
        float2 f;
        f = __half22float2(*(__half2*)&u.x); v[0] = f.x; v[1] = f.y;
        f = __half22float2(*(__half2*)&u.y); v[2] = f.x; v[3] = f.y;
        f = __half22float2(*(__half2*)&u.z); v[4] = f.x; v[5] = f.y;
        f = __half22float2(*(__half2*)&u.w); v[6] = f.x; v[7] = f.y;
    }
    float m = v[0];
#pragma unroll
    for (int j = 1; j < 8; j++) m = fmaxf(m, v[j]);
    red[t] = m;
    __syncthreads();
    for (int s = 128; s > 0; s >>= 1) {
        if (t < s) red[t] = fmaxf(red[t], red[t + s]);
        __syncthreads();
    }
    m = red[0];
    __syncthreads();

    float sum = 0.0f;
#pragma unroll
    for (int j = 0; j < 8; j++) {
        v[j] = __expf(v[j] - m);
        sum += v[j];
    }
    red[t] = sum;
    __syncthreads();
    for (int s = 128; s > 0; s >>= 1) {
        if (t < s) red[t] += red[t + s];
        __syncthreads();
    }
    const float inv = 1.0f / red[0];

    uint4 o;
    *(__half2*)&o.x = __floats2half2_rn(v[0] * inv, v[1] * inv);
    *(__half2*)&o.y = __floats2half2_rn(v[2] * inv, v[3] * inv);
    *(__half2*)&o.z = __floats2half2_rn(v[4] * inv, v[5] * inv);
    *(__half2*)&o.w = __floats2half2_rn(v[6] * inv, v[7] * inv);
    *(uint4*)&r[i] = o;
}

// ------------------------------ launch -------------------------------------
extern "C" void kernel_launch(void* const* d_in, const int* in_sizes, int n_in,
                              void* d_out, int out_size)
{
    (void)in_sizes; (void)n_in; (void)out_size;
    const float* x  = (const float*)d_in[0];
    const float* Wq = (const float*)d_in[1];
    const float* bq = (const float*)d_in[2];
    const float* Wk = (const float*)d_in[3];
    const float* bk = (const float*)d_in[4];
    const float* Wv = (const float*)d_in[5];
    const float* bv = (const float*)d_in[6];
    const float* Wo = (const float*)d_in[7];
    const float* bo = (const float*)d_in[8];
    float* out = (float*)d_out;

    __half *xh, *Wcat, *Woh, *QKV, *Sh, *Vth, *Oh;
    float* bcat;
    cudaGetSymbolAddress((void**)&xh,   g_xh);
    cudaGetSymbolAddress((void**)&Wcat, g_Wcat);
    cudaGetSymbolAddress((void**)&Woh,  g_Woh);
    cudaGetSymbolAddress((void**)&bcat, g_bcat);
    cudaGetSymbolAddress((void**)&QKV,  g_QKV);
    cudaGetSymbolAddress((void**)&Sh,   g_Sh);
    cudaGetSymbolAddress((void**)&Vth,  g_Vth);
    cudaGetSymbolAddress((void**)&Oh,   g_Oh);

    const int B = 4, T = 2048, D = 1024;
    const int M = B * T;
    const float scale = 0.03125f;   // 1/sqrt(1024)
    const long long sTT = (long long)T * T;
    const long long sTD = (long long)T * D;

    cudaFuncSetAttribute(tc_gemm<true,  false, true >,
                         cudaFuncAttributeMaxDynamicSharedMemorySize, SMEM_TOTAL);
    cudaFuncSetAttribute(tc_gemm<false, true,  true >,
                         cudaFuncAttributeMaxDynamicSharedMemorySize, SMEM_TOTAL);
    cudaFuncSetAttribute(tc_gemm<false, false, true >,
                         cudaFuncAttributeMaxDynamicSharedMemorySize, SMEM_TOTAL);
    cudaFuncSetAttribute(tc_gemm<true,  false, false>,
                         cudaFuncAttributeMaxDynamicSharedMemorySize, SMEM_TOTAL);

    // second stream + fork/join events (created fresh per call; host-side
    // resources only, kernel_launch is invoked O(1) times so no leak issue)
    cudaStream_t s1;
    cudaStreamCreateWithFlags(&s1, cudaStreamNonBlocking);
    cudaEvent_t eQKV, eT, eSc, eS1;
    cudaEventCreateWithFlags(&eQKV, cudaEventDisableTiming);
    cudaEventCreateWithFlags(&eT,   cudaEventDisableTiming);
    cudaEventCreateWithFlags(&eSc,  cudaEventDisableTiming);
    cudaEventCreateWithFlags(&eS1,  cudaEventDisableTiming);

    dim3 th(256);

    // 1) conversions + weight/bias concat                       [stream 0]
    prep<<<(unsigned)((PREP_TOTAL + 255) / 256), 256>>>(
        x, Wq, Wk, Wv, Wo, bq, bk, bv, xh, Wcat, Woh, bcat);

    // 2) fused QKV projection: [8192,3072] = xh @ Wcat^T + bcat [stream 0]
    tc_gemm<true, false, true><<<dim3(3072 / BN, M / BM, 1), th, SMEM_TOTAL>>>(
        xh, Wcat, bcat, QKV, M, 3072, D, D, D, 3072, 1.0f, 0, 0, 0);
    cudaEventRecord(eQKV, 0);

    // 3) Vt[b] = V[b]^T  on s1, concurrent with scores
    cudaStreamWaitEvent(s1, eQKV, 0);
    transpose_h<<<dim3(D / 32, T / 32, B), 256, 0, s1>>>(QKV, Vth);
    cudaEventRecord(eT, s1);

    // 4) scores (half out, scaled): S[b] = (Q[b] @ K[b]^T)/32   [stream 0]
    tc_gemm<false, true, true><<<dim3(T / BN, T / BM, B), th, SMEM_TOTAL>>>(
        QKV, QKV + 1024, nullptr, Sh, T, T, D, 3072, 3072, T, scale,
        (long long)T * 3072, (long long)T * 3072, sTT);
    cudaEventRecord(eSc, 0);

    // 5+6) per-batch softmax -> PV, interleaved on two streams
    cudaStreamWaitEvent(s1, eSc, 0);   // s1 already did transpose
    cudaStreamWaitEvent(0,  eT,  0);   // stream-0 PVs need Vt
    for (int b = 0; b < 4; b++) {
        cudaStream_t sb = (b & 1) ? s1 : (cudaStream_t)0;
        softmax_h<<<T, 256, 0, sb>>>(Sh + (long long)b * sTT, T);
        tc_gemm<false, false, true><<<dim3(D / BN, T / BM, 1), th, SMEM_TOTAL, sb>>>(
            Sh + (long long)b * sTT, Vth + (long long)b * sTD, nullptr,
            Oh + (long long)b * sTD, T, D, T, T, T, D, 1.0f, 0, 0, 0);
    }
    cudaEventRecord(eS1, s1);
    cudaStreamWaitEvent(0, eS1, 0);    // join

    // 7) out = O @ Wo^T + bo (fp32 out)                         [stream 0]
    tc_gemm<true, false, false><<<dim3(D / BN, M / BM, 1), th, SMEM_TOTAL>>>(
        Oh, Woh, bo, out, M, D, D, D, D, D, 1.0f, 0, 0, 0);
}

// round 8
// speedup vs baseline: 1.0618x; 1.0618x over previous
#include <cuda_runtime.h>
#include <cuda_fp16.h>
#include <cstdint>
#include <math.h>

// ------------------------------ scratch ------------------------------------
__device__ __half g_xh  [8192 * 1024];
__device__ __half g_Wcat[3 * 1024 * 1024];          // [Wq;Wk;Wv] as [3072,1024]
__device__ __half g_Woh [1024 * 1024];
__device__ float  g_bcat[3072];                     // [bq;bk;bv]
__device__ __half g_QKV [8192LL * 3072];            // per row: [Q|K|V]
__device__ __half g_Sh  [4LL * 2048 * 2048];        // scores -> softmax in place
__device__ __half g_Vth [8192 * 1024];              // V^T per batch [1024,2048]
__device__ __half g_Oh  [8192 * 1024];

// ------------------------------ helpers ------------------------------------
__device__ __forceinline__ uint32_t smem_u32(const void* p) {
    uint32_t a;
    asm("{ .reg .u64 t; cvta.to.shared.u64 t, %1; cvt.u32.u64 %0, t; }"
        : "=r"(a) : "l"(p));
    return a;
}
__device__ __forceinline__ void ldsm4(uint32_t& r0, uint32_t& r1,
                                      uint32_t& r2, uint32_t& r3, uint32_t a) {
    asm volatile("ldmatrix.sync.aligned.m8n8.x4.shared.b16 {%0,%1,%2,%3}, [%4];"
                 : "=r"(r0), "=r"(r1), "=r"(r2), "=r"(r3) : "r"(a));
}
__device__ __forceinline__ void mma_f16(float* d, const uint32_t* a,
                                        const uint32_t* b) {
    asm volatile(
        "mma.sync.aligned.m16n8k16.row.col.f32.f16.f16.f32 "
        "{%0,%1,%2,%3}, {%4,%5,%6,%7}, {%8,%9}, {%0,%1,%2,%3};"
        : "+f"(d[0]), "+f"(d[1]), "+f"(d[2]), "+f"(d[3])
        : "r"(a[0]), "r"(a[1]), "r"(a[2]), "r"(a[3]), "r"(b[0]), "r"(b[1]));
}
#define CP_ASYNC16(s, g) \
    asm volatile("cp.async.cg.shared.global [%0], [%1], 16;" :: "r"(s), "l"(g))
#define CP_COMMIT()  asm volatile("cp.async.commit_group;" ::: "memory")
#define CP_WAIT1()   asm volatile("cp.async.wait_group 1;" ::: "memory")

// ------------------------------ GEMM ---------------------------------------
// C[M,N] = A[M,K] @ B[N,K]^T (half in, fp16 MMA, fp32 acc). Row strides lda/ldb/ldc.
// 128x128 block tile, BK=64, 3-stage cp.async, 8 warps (2m x 4n), warp 64x32.
// Small tiles -> large grids -> minimal wave-quantization tails.
static constexpr int BM = 128, BN = 128, BK = 64, STAGES = 3;
static constexpr int AB_BYTES    = BM * BK * 2;            // 16384
static constexpr int STAGE_BYTES = 2 * AB_BYTES;           // 32768
static constexpr int SMEM_TOTAL  = STAGES * STAGE_BYTES;   // 98304

// swizzled byte offset of (row, 16B-quad q) in a [rows][64 halves] tile
__device__ __forceinline__ uint32_t swz(int r, int q) {
    return (uint32_t)(r * 128 + ((q ^ (r & 7)) << 4));
}

template <bool BIAS, bool SCALE, bool OUTH>
__global__ __launch_bounds__(256, 2) void tc_gemm(
    const __half* __restrict__ A, const __half* __restrict__ Bm,
    const float* __restrict__ bias, void* __restrict__ Cv,
    int M, int N, int K, int lda, int ldb, int ldc, float scale,
    long long sA, long long sB, long long sC)
{
    extern __shared__ __align__(1024) char smem[];
    const uint32_t sb = smem_u32(smem);

    const int tid  = threadIdx.x;
    const int lane = tid & 31;
    const int wid  = tid >> 5;
    const int wm   = (wid >> 2) * 64;   // 0 or 64
    const int wn   = (wid & 3) * 32;    // 0,32,64,96

    const long long bz = blockIdx.z;
    A  += bz * sA;
    Bm += bz * sB;
    const int m0 = blockIdx.y * BM;
    const int n0 = blockIdx.x * BN;
    const int nchunks = K / BK;

    const int midx = lane >> 3, l7 = lane & 7;
    int aR[4];
#pragma unroll
    for (int mi = 0; mi < 4; mi++) aR[mi] = wm + mi * 16 + ((midx & 1) << 3) + l7;
    const int aKH = midx >> 1;
    int bR[2];
#pragma unroll
    for (int n2 = 0; n2 < 2; n2++) bR[n2] = wn + n2 * 16 + ((midx >> 1) << 3) + l7;
    const int bKH = midx & 1;

    float acc[4][4][4];
#pragma unroll
    for (int mi = 0; mi < 4; mi++)
#pragma unroll
        for (int ni = 0; ni < 4; ni++)
#pragma unroll
            for (int j = 0; j < 4; j++) acc[mi][ni][j] = 0.0f;

    auto issue = [&](int c) {
        if (c < nchunks) {
            const int s = c % STAGES;
            const uint32_t As = sb + s * STAGE_BYTES;
            const uint32_t Bs = As + AB_BYTES;
            const int k0 = c * BK;
#pragma unroll
            for (int i = tid; i < 2048; i += 256) {
                const int idx = i & 1023;
                const int r = idx >> 3, q = idx & 7;
                if (i < 1024) {
                    CP_ASYNC16(As + swz(r, q),
                               A + (long long)(m0 + r) * lda + k0 + q * 8);
                } else {
                    CP_ASYNC16(Bs + swz(r, q),
                               Bm + (long long)(n0 + r) * ldb + k0 + q * 8);
                }
            }
        }
        CP_COMMIT();
    };

    issue(0);
    issue(1);

    for (int c = 0; c < nchunks; c++) {
        CP_WAIT1();
        __syncthreads();
        issue(c + 2);

        const int s = c % STAGES;
        const uint32_t As = sb + s * STAGE_BYTES;
        const uint32_t Bs = As + AB_BYTES;

#pragma unroll
        for (int kk = 0; kk < 4; kk++) {        // 4 x k16
            uint32_t aF[4][4], bF[4][2];
#pragma unroll
            for (int mi = 0; mi < 4; mi++)
                ldsm4(aF[mi][0], aF[mi][1], aF[mi][2], aF[mi][3],
                      As + swz(aR[mi], kk * 2 + aKH));
#pragma unroll
            for (int n2 = 0; n2 < 2; n2++) {
                uint32_t r0, r1, r2, r3;
                ldsm4(r0, r1, r2, r3, Bs + swz(bR[n2], kk * 2 + bKH));
                bF[n2 * 2 + 0][0] = r0;
                bF[n2 * 2 + 0][1] = r1;
                bF[n2 * 2 + 1][0] = r2;
                bF[n2 * 2 + 1][1] = r3;
            }
#pragma unroll
            for (int mi = 0; mi < 4; mi++)
#pragma unroll
                for (int ni = 0; ni < 4; ni++)
                    mma_f16(acc[mi][ni], aF[mi], bF[ni]);
        }
    }

    // ------------------ epilogue ------------------
    const int crow = lane >> 2;
    const int ccol = (lane & 3) * 2;
#pragma unroll
    for (int mi = 0; mi < 4; mi++) {
#pragma unroll
        for (int ni = 0; ni < 4; ni++) {
            const int col = n0 + wn + ni * 8 + ccol;
            float2 b2 = make_float2(0.f, 0.f);
            if (BIAS) b2 = *(const float2*)&bias[col];
#pragma unroll
            for (int h = 0; h < 2; h++) {
                const int row = m0 + wm + mi * 16 + crow + h * 8;
                float vx = acc[mi][ni][h * 2 + 0];
                float vy = acc[mi][ni][h * 2 + 1];
                if (SCALE) { vx *= scale; vy *= scale; }
                if (BIAS)  { vx += b2.x;  vy += b2.y; }
                if (OUTH) {
                    __half2* C = (__half2*)((__half*)Cv + bz * sC);
                    C[((long long)row * ldc + col) >> 1] = __floats2half2_rn(vx, vy);
                } else {
                    float* C = (float*)Cv + bz * sC;
                    *(float2*)&C[(long long)row * ldc + col] = make_float2(vx, vy);
                }
            }
        }
    }
}

// ------------------------------ prep (all conversions in one) --------------
static constexpr long long XG = 8192LL * 1024 / 4;      // float4 groups of x
static constexpr long long WG = 1024LL * 1024 / 4;      // per weight
static constexpr long long PREP_TOTAL = XG + 4 * WG + 768;

__global__ __launch_bounds__(256) void prep(
    const float* __restrict__ x,
    const float* __restrict__ Wq, const float* __restrict__ Wk,
    const float* __restrict__ Wv, const float* __restrict__ Wo,
    const float* __restrict__ bq, const float* __restrict__ bk,
    const float* __restrict__ bv,
    __half* __restrict__ xh, __half* __restrict__ Wcat,
    __half* __restrict__ Woh, float* __restrict__ bcat)
{
    const long long g = (long long)blockIdx.x * 256 + threadIdx.x;
    if (g >= PREP_TOTAL) return;

    const float* s;
    __half* d;
    long long off;
    if (g < XG)              { s = x;  d = xh;             off = g; }
    else if (g < XG + WG)    { s = Wq; d = Wcat;           off = g - XG; }
    else if (g < XG + 2*WG)  { s = Wk; d = Wcat + 1048576; off = g - XG - WG; }
    else if (g < XG + 3*WG)  { s = Wv; d = Wcat + 2097152; off = g - XG - 2*WG; }
    else if (g < XG + 4*WG)  { s = Wo; d = Woh;            off = g - XG - 3*WG; }
    else {
        const long long idx = (g - XG - 4*WG) * 4;      // 0..3068
        const float* bs = (idx < 1024) ? bq + idx
                        : (idx < 2048) ? bk + (idx - 1024)
                                       : bv + (idx - 2048);
        *(float4*)&bcat[idx] = *(const float4*)bs;
        return;
    }
    float4 v = *(const float4*)&s[off * 4];
    *(__half2*)&d[off * 4]     = __floats2half2_rn(v.x, v.y);
    *(__half2*)&d[off * 4 + 2] = __floats2half2_rn(v.z, v.w);
}

// ------------------------------ transpose ----------------------------------
// Vth[b][d][t] = QKV[b*T + t][2048 + d]
__global__ __launch_bounds__(256) void transpose_h(
    const __half* __restrict__ QKV, __half* __restrict__ Vt)
{
    __shared__ __half tile[32][33];
    const long long b = blockIdx.z;
    const __half* src = QKV + b * 2048LL * 3072 + 2048;
    __half* dst = Vt + b * 2048LL * 1024;
    const int x0 = blockIdx.x * 32;   // d
    const int y0 = blockIdx.y * 32;   // t
    const int tx = threadIdx.x & 31;
    const int ty = threadIdx.x >> 5;
#pragma unroll
    for (int i = 0; i < 32; i += 8)
        tile[ty + i][tx] = src[(long long)(y0 + ty + i) * 3072 + x0 + tx];
    __syncthreads();
#pragma unroll
    for (int i = 0; i < 32; i += 8)
        dst[(long long)(x0 + ty + i) * 2048 + y0 + tx] = tile[tx][ty + i];
}

// ------------------------------ softmax (half, in place) -------------------
__global__ __launch_bounds__(256) void softmax_h(__half* __restrict__ S, int T)
{
    __shared__ float red[256];
    const long long row = blockIdx.x;
    __half* r = S + row * T;
    const int t = threadIdx.x;
    const int i = t * 8;                       // 8 halves per thread, T=2048

    uint4 u = *(const uint4*)&r[i];
    float v[8];
    {
        float2 f;
        f = __half22float2(*(__half2*)&u.x); v[0] = f.x; v[1] = f.y;
        f = __half22float2(*(__half2*)&u.y); v[2] = f.x; v[3] = f.y;
        f = __half22float2(*(__half2*)&u.z); v[4] = f.x; v[5] = f.y;
        f = __half22float2(*(__half2*)&u.w); v[6] = f.x; v[7] = f.y;
    }
    float m = v[0];
#pragma unroll
    for (int j = 1; j < 8; j++) m = fmaxf(m, v[j]);
    red[t] = m;
    __syncthreads();
    for (int s = 128; s > 0; s >>= 1) {
        if (t < s) red[t] = fmaxf(red[t], red[t + s]);
        __syncthreads();
    }
    m = red[0];
    __syncthreads();

    float sum = 0.0f;
#pragma unroll
    for (int j = 0; j < 8; j++) {
        v[j] = __expf(v[j] - m);
        sum += v[j];
    }
    red[t] = sum;
    __syncthreads();
    for (int s = 128; s > 0; s >>= 1) {
        if (t < s) red[t] += red[t + s];
        __syncthreads();
    }
    const float inv = 1.0f / red[0];

    uint4 o;
    *(__half2*)&o.x = __floats2half2_rn(v[0] * inv, v[1] * inv);
    *(__half2*)&o.y = __floats2half2_rn(v[2] * inv, v[3] * inv);
    *(__half2*)&o.z = __floats2half2_rn(v[4] * inv, v[5] * inv);
    *(__half2*)&o.w = __floats2half2_rn(v[6] * inv, v[7] * inv);
    *(uint4*)&r[i] = o;
}

// ------------------------------ launch -------------------------------------
extern "C" void kernel_launch(void* const* d_in, const int* in_sizes, int n_in,
                              void* d_out, int out_size)
{
    (void)in_sizes; (void)n_in; (void)out_size;
    const float* x  = (const float*)d_in[0];
    const float* Wq = (const float*)d_in[1];
    const float* bq = (const float*)d_in[2];
    const float* Wk = (const float*)d_in[3];
    const float* bk = (const float*)d_in[4];
    const float* Wv = (const float*)d_in[5];
    const float* bv = (const float*)d_in[6];
    const float* Wo = (const float*)d_in[7];
    const float* bo = (const float*)d_in[8];
    float* out = (float*)d_out;

    __half *xh, *Wcat, *Woh, *QKV, *Sh, *Vth, *Oh;
    float* bcat;
    cudaGetSymbolAddress((void**)&xh,   g_xh);
    cudaGetSymbolAddress((void**)&Wcat, g_Wcat);
    cudaGetSymbolAddress((void**)&Woh,  g_Woh);
    cudaGetSymbolAddress((void**)&bcat, g_bcat);
    cudaGetSymbolAddress((void**)&QKV,  g_QKV);
    cudaGetSymbolAddress((void**)&Sh,   g_Sh);
    cudaGetSymbolAddress((void**)&Vth,  g_Vth);
    cudaGetSymbolAddress((void**)&Oh,   g_Oh);

    const int B = 4, T = 2048, D = 1024;
    const int M = B * T;
    const float scale = 0.03125f;   // 1/sqrt(1024)
    const long long sTT = (long long)T * T;
    const long long sTD = (long long)T * D;

    cudaFuncSetAttribute(tc_gemm<true,  false, true >,
                         cudaFuncAttributeMaxDynamicSharedMemorySize, SMEM_TOTAL);
    cudaFuncSetAttribute(tc_gemm<false, true,  true >,
                         cudaFuncAttributeMaxDynamicSharedMemorySize, SMEM_TOTAL);
    cudaFuncSetAttribute(tc_gemm<false, false, true >,
                         cudaFuncAttributeMaxDynamicSharedMemorySize, SMEM_TOTAL);
    cudaFuncSetAttribute(tc_gemm<true,  false, false>,
                         cudaFuncAttributeMaxDynamicSharedMemorySize, SMEM_TOTAL);

    dim3 th(256);

    // 1) conversions + weight/bias concat
    prep<<<(unsigned)((PREP_TOTAL + 255) / 256), 256>>>(
        x, Wq, Wk, Wv, Wo, bq, bk, bv, xh, Wcat, Woh, bcat);

    // 2) fused QKV projection: [8192,3072] = xh @ Wcat^T + bcat  (1536 CTAs)
    tc_gemm<true, false, true><<<dim3(3072 / BN, M / BM, 1), th, SMEM_TOTAL>>>(
        xh, Wcat, bcat, QKV, M, 3072, D, D, D, 3072, 1.0f, 0, 0, 0);

    // 3) Vt[b] = V[b]^T
    transpose_h<<<dim3(D / 32, T / 32, B), 256>>>(QKV, Vth);

    // 4) scores: S[b] = (Q[b] @ K[b]^T)/32   (half out, 1024 CTAs)
    tc_gemm<false, true, true><<<dim3(T / BN, T / BM, B), th, SMEM_TOTAL>>>(
        QKV, QKV + 1024, nullptr, Sh, T, T, D, 3072, 3072, T, scale,
        (long long)T * 3072, (long long)T * 3072, sTT);

    // 5) softmax in place on half rows
    softmax_h<<<B * T, 256>>>(Sh, T);

    // 6) O = P @ Vt^T   (half out, 512 CTAs)
    tc_gemm<false, false, true><<<dim3(D / BN, T / BM, B), th, SMEM_TOTAL>>>(
        Sh, Vth, nullptr, Oh, T, D, T, T, T, D, 1.0f, sTT, sTD, sTD);

    // 7) out = O @ Wo^T + bo   (fp32 out, 512 CTAs)
    tc_gemm<true, false, false><<<dim3(D / BN, M / BM, 1), th, SMEM_TOTAL>>>(
        Oh, Woh, bo, out, M, D, D, D, D, D, 1.0f, 0, 0, 0);
}

// round 9
// speedup vs baseline: 1.1346x; 1.0685x over previous
#include <cuda_runtime.h>
#include <cuda_fp16.h>
#include <cstdint>
#include <math.h>

// ------------------------------ scratch ------------------------------------
__device__ __half g_xh  [8192 * 1024];
__device__ __half g_Wcat[3 * 1024 * 1024];          // [Wq;Wk;Wv] as [3072,1024]
__device__ __half g_Woh [1024 * 1024];
__device__ float  g_bcat[3072];                     // [bq;bk;bv]
__device__ __half g_QKV [8192LL * 3072];            // per row: [Q|K|V]
__device__ __half g_Sh  [4LL * 2048 * 2048];        // scores -> softmax in place
__device__ __half g_Vth [8192 * 1024];              // V^T per batch [1024,2048]
__device__ __half g_Oh  [8192 * 1024];

// ------------------------------ helpers ------------------------------------
__device__ __forceinline__ uint32_t smem_u32(const void* p) {
    uint32_t a;
    asm("{ .reg .u64 t; cvta.to.shared.u64 t, %1; cvt.u32.u64 %0, t; }"
        : "=r"(a) : "l"(p));
    return a;
}
__device__ __forceinline__ void ldsm4(uint32_t& r0, uint32_t& r1,
                                      uint32_t& r2, uint32_t& r3, uint32_t a) {
    asm volatile("ldmatrix.sync.aligned.m8n8.x4.shared.b16 {%0,%1,%2,%3}, [%4];"
                 : "=r"(r0), "=r"(r1), "=r"(r2), "=r"(r3) : "r"(a));
}
__device__ __forceinline__ void mma_f16(float* d, const uint32_t* a,
                                        const uint32_t* b) {
    asm volatile(
        "mma.sync.aligned.m16n8k16.row.col.f32.f16.f16.f32 "
        "{%0,%1,%2,%3}, {%4,%5,%6,%7}, {%8,%9}, {%0,%1,%2,%3};"
        : "+f"(d[0]), "+f"(d[1]), "+f"(d[2]), "+f"(d[3])
        : "r"(a[0]), "r"(a[1]), "r"(a[2]), "r"(a[3]), "r"(b[0]), "r"(b[1]));
}
#define CP_ASYNC16(s, g) \
    asm volatile("cp.async.cg.shared.global [%0], [%1], 16;" :: "r"(s), "l"(g))
#define CP_COMMIT()  asm volatile("cp.async.commit_group;" ::: "memory")
#define CP_WAIT1()   asm volatile("cp.async.wait_group 1;" ::: "memory")

// ------------------------------ GEMM ---------------------------------------
// C[M,N] = A[M,K] @ B[N,K]^T (half in, fp16 MMA, fp32 acc). Row strides lda/ldb/ldc.
// 128x128 block tile, BK=64, 3-stage cp.async.
// 4 warps (2m x 2n), warp tile 64x64 -> minimal smem fragment re-reads,
// 128 threads/CTA so that 2 CTAs co-reside per SM (two barrier domains).
static constexpr int BM = 128, BN = 128, BK = 64, STAGES = 3;
static constexpr int AB_BYTES    = BM * BK * 2;            // 16384
static constexpr int STAGE_BYTES = 2 * AB_BYTES;           // 32768
static constexpr int SMEM_TOTAL  = STAGES * STAGE_BYTES;   // 98304

// swizzled byte offset of (row, 16B-quad q) in a [rows][64 halves] tile
__device__ __forceinline__ uint32_t swz(int r, int q) {
    return (uint32_t)(r * 128 + ((q ^ (r & 7)) << 4));
}

template <bool BIAS, bool SCALE, bool OUTH>
__global__ __launch_bounds__(128, 2) void tc_gemm(
    const __half* __restrict__ A, const __half* __restrict__ Bm,
    const float* __restrict__ bias, void* __restrict__ Cv,
    int M, int N, int K, int lda, int ldb, int ldc, float scale,
    long long sA, long long sB, long long sC)
{
    extern __shared__ __align__(1024) char smem[];
    const uint32_t sb = smem_u32(smem);

    const int tid  = threadIdx.x;
    const int lane = tid & 31;
    const int wid  = tid >> 5;          // 0..3
    const int wm   = (wid >> 1) * 64;   // 0 or 64
    const int wn   = (wid & 1) * 64;    // 0 or 64

    const long long bz = blockIdx.z;
    A  += bz * sA;
    Bm += bz * sB;
    const int m0 = blockIdx.y * BM;
    const int n0 = blockIdx.x * BN;
    const int nchunks = K / BK;

    const int midx = lane >> 3, l7 = lane & 7;
    int aR[4];
#pragma unroll
    for (int mi = 0; mi < 4; mi++) aR[mi] = wm + mi * 16 + ((midx & 1) << 3) + l7;
    const int aKH = midx >> 1;
    int bR[4];
#pragma unroll
    for (int n2 = 0; n2 < 4; n2++) bR[n2] = wn + n2 * 16 + ((midx >> 1) << 3) + l7;
    const int bKH = midx & 1;

    float acc[4][8][4];
#pragma unroll
    for (int mi = 0; mi < 4; mi++)
#pragma unroll
        for (int ni = 0; ni < 8; ni++)
#pragma unroll
            for (int j = 0; j < 4; j++) acc[mi][ni][j] = 0.0f;

    auto issue = [&](int c) {
        if (c < nchunks) {
            const int s = c % STAGES;
            const uint32_t As = sb + s * STAGE_BYTES;
            const uint32_t Bs = As + AB_BYTES;
            const int k0 = c * BK;
#pragma unroll
            for (int i = tid; i < 2048; i += 128) {
                const int idx = i & 1023;
                const int r = idx >> 3, q = idx & 7;
                if (i < 1024) {
                    CP_ASYNC16(As + swz(r, q),
                               A + (long long)(m0 + r) * lda + k0 + q * 8);
                } else {
                    CP_ASYNC16(Bs + swz(r, q),
                               Bm + (long long)(n0 + r) * ldb + k0 + q * 8);
                }
            }
        }
        CP_COMMIT();
    };

    issue(0);
    issue(1);

    for (int c = 0; c < nchunks; c++) {
        CP_WAIT1();
        __syncthreads();
        issue(c + 2);

        const int s = c % STAGES;
        const uint32_t As = sb + s * STAGE_BYTES;
        const uint32_t Bs = As + AB_BYTES;

#pragma unroll
        for (int kk = 0; kk < 4; kk++) {        // 4 x k16
            uint32_t aF[4][4], bF[8][2];
#pragma unroll
            for (int mi = 0; mi < 4; mi++)
                ldsm4(aF[mi][0], aF[mi][1], aF[mi][2], aF[mi][3],
                      As + swz(aR[mi], kk * 2 + aKH));
#pragma unroll
            for (int n2 = 0; n2 < 4; n2++) {
                uint32_t r0, r1, r2, r3;
                ldsm4(r0, r1, r2, r3, Bs + swz(bR[n2], kk * 2 + bKH));
                bF[n2 * 2 + 0][0] = r0;
                bF[n2 * 2 + 0][1] = r1;
                bF[n2 * 2 + 1][0] = r2;
                bF[n2 * 2 + 1][1] = r3;
            }
#pragma unroll
            for (int mi = 0; mi < 4; mi++)
#pragma unroll
                for (int ni = 0; ni < 8; ni++)
                    mma_f16(acc[mi][ni], aF[mi], bF[ni]);
        }
    }

    // ------------------ epilogue ------------------
    const int crow = lane >> 2;
    const int ccol = (lane & 3) * 2;
#pragma unroll
    for (int mi = 0; mi < 4; mi++) {
#pragma unroll
        for (int ni = 0; ni < 8; ni++) {
            const int col = n0 + wn + ni * 8 + ccol;
            float2 b2 = make_float2(0.f, 0.f);
            if (BIAS) b2 = *(const float2*)&bias[col];
#pragma unroll
            for (int h = 0; h < 2; h++) {
                const int row = m0 + wm + mi * 16 + crow + h * 8;
                float vx = acc[mi][ni][h * 2 + 0];
                float vy = acc[mi][ni][h * 2 + 1];
                if (SCALE) { vx *= scale; vy *= scale; }
                if (BIAS)  { vx += b2.x;  vy += b2.y; }
                if (OUTH) {
                    __half2* C = (__half2*)((__half*)Cv + bz * sC);
                    C[((long long)row * ldc + col) >> 1] = __floats2half2_rn(vx, vy);
                } else {
                    float* C = (float*)Cv + bz * sC;
                    *(float2*)&C[(long long)row * ldc + col] = make_float2(vx, vy);
                }
            }
        }
    }
}

// ------------------------------ prep (all conversions in one) --------------
static constexpr long long XG = 8192LL * 1024 / 4;      // float4 groups of x
static constexpr long long WG = 1024LL * 1024 / 4;      // per weight
static constexpr long long PREP_TOTAL = XG + 4 * WG + 768;

__global__ __launch_bounds__(256) void prep(
    const float* __restrict__ x,
    const float* __restrict__ Wq, const float* __restrict__ Wk,
    const float* __restrict__ Wv, const float* __restrict__ Wo,
    const float* __restrict__ bq, const float* __restrict__ bk,
    const float* __restrict__ bv,
    __half* __restrict__ xh, __half* __restrict__ Wcat,
    __half* __restrict__ Woh, float* __restrict__ bcat)
{
    const long long g = (long long)blockIdx.x * 256 + threadIdx.x;
    if (g >= PREP_TOTAL) return;

    const float* s;
    __half* d;
    long long off;
    if (g < XG)              { s = x;  d = xh;             off = g; }
    else if (g < XG + WG)    { s = Wq; d = Wcat;           off = g - XG; }
    else if (g < XG + 2*WG)  { s = Wk; d = Wcat + 1048576; off = g - XG - WG; }
    else if (g < XG + 3*WG)  { s = Wv; d = Wcat + 2097152; off = g - XG - 2*WG; }
    else if (g < XG + 4*WG)  { s = Wo; d = Woh;            off = g - XG - 3*WG; }
    else {
        const long long idx = (g - XG - 4*WG) * 4;      // 0..3068
        const float* bs = (idx < 1024) ? bq + idx
                        : (idx < 2048) ? bk + (idx - 1024)
                                       : bv + (idx - 2048);
        *(float4*)&bcat[idx] = *(const float4*)bs;
        return;
    }
    float4 v = *(const float4*)&s[off * 4];
    *(__half2*)&d[off * 4]     = __floats2half2_rn(v.x, v.y);
    *(__half2*)&d[off * 4 + 2] = __floats2half2_rn(v.z, v.w);
}

// ------------------------------ transpose ----------------------------------
// Vth[b][d][t] = QKV[b*T + t][2048 + d]
__global__ __launch_bounds__(256) void transpose_h(
    const __half* __restrict__ QKV, __half* __restrict__ Vt)
{
    __shared__ __half tile[32][33];
    const long long b = blockIdx.z;
    const __half* src = QKV + b * 2048LL * 3072 + 2048;
    __half* dst = Vt + b * 2048LL * 1024;
    const int x0 = blockIdx.x * 32;   // d
    const int y0 = blockIdx.y * 32;   // t
    const int tx = threadIdx.x & 31;
    const int ty = threadIdx.x >> 5;
#pragma unroll
    for (int i = 0; i < 32; i += 8)
        tile[ty + i][tx] = src[(long long)(y0 + ty + i) * 3072 + x0 + tx];
    __syncthreads();
#pragma unroll
    for (int i = 0; i < 32; i += 8)
        dst[(long long)(x0 + ty + i) * 2048 + y0 + tx] = tile[tx][ty + i];
}

// ------------------------------ softmax (half, in place) -------------------
__global__ __launch_bounds__(256) void softmax_h(__half* __restrict__ S, int T)
{
    __shared__ float red[256];
    const long long row = blockIdx.x;
    __half* r = S + row * T;
    const int t = threadIdx.x;
    const int i = t * 8;                       // 8 halves per thread, T=2048

    uint4 u = *(const uint4*)&r[i];
    float v[8];
    {
        float2 f;
        f = __half22float2(*(__half2*)&u.x); v[0] = f.x; v[1] = f.y;
        f = __half22float2(*(__half2*)&u.y); v[2] = f.x; v[3] = f.y;
        f = __half22float2(*(__half2*)&u.z); v[4] = f.x; v[5] = f.y;
        f = __half22float2(*(__half2*)&u.w); v[6] = f.x; v[7] = f.y;
    }
    float m = v[0];
#pragma unroll
    for (int j = 1; j < 8; j++) m = fmaxf(m, v[j]);
    red[t] = m;
    __syncthreads();
    for (int s = 128; s > 0; s >>= 1) {
        if (t < s) red[t] = fmaxf(red[t], red[t + s]);
        __syncthreads();
    }
    m = red[0];
    __syncthreads();

    float sum = 0.0f;
#pragma unroll
    for (int j = 0; j < 8; j++) {
        v[j] = __expf(v[j] - m);
        sum += v[j];
    }
    red[t] = sum;
    __syncthreads();
    for (int s = 128; s > 0; s >>= 1) {
        if (t < s) red[t] += red[t + s];
        __syncthreads();
    }
    const float inv = 1.0f / red[0];

    uint4 o;
    *(__half2*)&o.x = __floats2half2_rn(v[0] * inv, v[1] * inv);
    *(__half2*)&o.y = __floats2half2_rn(v[2] * inv, v[3] * inv);
    *(__half2*)&o.z = __floats2half2_rn(v[4] * inv, v[5] * inv);
    *(__half2*)&o.w = __floats2half2_rn(v[6] * inv, v[7] * inv);
    *(uint4*)&r[i] = o;
}

// ------------------------------ launch -------------------------------------
extern "C" void kernel_launch(void* const* d_in, const int* in_sizes, int n_in,
                              void* d_out, int out_size)
{
    (void)in_sizes; (void)n_in; (void)out_size;
    const float* x  = (const float*)d_in[0];
    const float* Wq = (const float*)d_in[1];
    const float* bq = (const float*)d_in[2];
    const float* Wk = (const float*)d_in[3];
    const float* bk = (const float*)d_in[4];
    const float* Wv = (const float*)d_in[5];
    const float* bv = (const float*)d_in[6];
    const float* Wo = (const float*)d_in[7];
    const float* bo = (const float*)d_in[8];
    float* out = (float*)d_out;

    __half *xh, *Wcat, *Woh, *QKV, *Sh, *Vth, *Oh;
    float* bcat;
    cudaGetSymbolAddress((void**)&xh,   g_xh);
    cudaGetSymbolAddress((void**)&Wcat, g_Wcat);
    cudaGetSymbolAddress((void**)&Woh,  g_Woh);
    cudaGetSymbolAddress((void**)&bcat, g_bcat);
    cudaGetSymbolAddress((void**)&QKV,  g_QKV);
    cudaGetSymbolAddress((void**)&Sh,   g_Sh);
    cudaGetSymbolAddress((void**)&Vth,  g_Vth);
    cudaGetSymbolAddress((void**)&Oh,   g_Oh);

    const int B = 4, T = 2048, D = 1024;
    const int M = B * T;
    const float scale = 0.03125f;   // 1/sqrt(1024)
    const long long sTT = (long long)T * T;
    const long long sTD = (long long)T * D;

    cudaFuncSetAttribute(tc_gemm<true,  false, true >,
                         cudaFuncAttributeMaxDynamicSharedMemorySize, SMEM_TOTAL);
    cudaFuncSetAttribute(tc_gemm<false, true,  true >,
                         cudaFuncAttributeMaxDynamicSharedMemorySize, SMEM_TOTAL);
    cudaFuncSetAttribute(tc_gemm<false, false, true >,
                         cudaFuncAttributeMaxDynamicSharedMemorySize, SMEM_TOTAL);
    cudaFuncSetAttribute(tc_gemm<true,  false, false>,
                         cudaFuncAttributeMaxDynamicSharedMemorySize, SMEM_TOTAL);

    dim3 th(128);

    // 1) conversions + weight/bias concat
    prep<<<(unsigned)((PREP_TOTAL + 255) / 256), 256>>>(
        x, Wq, Wk, Wv, Wo, bq, bk, bv, xh, Wcat, Woh, bcat);

    // 2) fused QKV projection: [8192,3072] = xh @ Wcat^T + bcat  (1536 CTAs)
    tc_gemm<true, false, true><<<dim3(3072 / BN, M / BM, 1), th, SMEM_TOTAL>>>(
        xh, Wcat, bcat, QKV, M, 3072, D, D, D, 3072, 1.0f, 0, 0, 0);

    // 3) Vt[b] = V[b]^T
    transpose_h<<<dim3(D / 32, T / 32, B), 256>>>(QKV, Vth);

    // 4) scores: S[b] = (Q[b] @ K[b]^T)/32   (half out, 1024 CTAs)
    tc_gemm<false, true, true><<<dim3(T / BN, T / BM, B), th, SMEM_TOTAL>>>(
        QKV, QKV + 1024, nullptr, Sh, T, T, D, 3072, 3072, T, scale,
        (long long)T * 3072, (long long)T * 3072, sTT);

    // 5) softmax in place on half rows
    softmax_h<<<B * T, 256>>>(Sh, T);

    // 6) O = P @ Vt^T   (half out, 512 CTAs)
    tc_gemm<false, false, true><<<dim3(D / BN, T / BM, B), th, SMEM_TOTAL>>>(
        Sh, Vth, nullptr, Oh, T, D, T, T, T, D, 1.0f, sTT, sTD, sTD);

    // 7) out = O @ Wo^T + bo   (fp32 out, 512 CTAs)
    tc_gemm<true, false, false><<<dim3(D / BN, M / BM, 1), th, SMEM_TOTAL>>>(
        Oh, Woh, bo, out, M, D, D, D, D, D, 1.0f, 0, 0, 0);
}

// round 11
// speedup vs baseline: 1.2509x; 1.1025x over previous
#include <cuda_runtime.h>
#include <cuda_fp16.h>
#include <cstdint>
#include <math.h>

// ------------------------------ scratch ------------------------------------
__device__ __half g_xh  [8192 * 1024];
__device__ __half g_Wcat[3 * 1024 * 1024];          // [Wq;Wk;Wv] as [3072,1024]
__device__ __half g_Woh [1024 * 1024];
__device__ float  g_bcat[3072];                     // [bq;bk;bv]
__device__ __half g_QKV [8192LL * 3072];            // per row: [Q|K|V]
__device__ __half g_Sh  [4LL * 2048 * 2048];        // scores -> softmax in place
__device__ __half g_Vth [8192 * 1024];              // V^T per batch [1024,2048]
__device__ __half g_Oh  [8192 * 1024];

// ------------------------------ helpers ------------------------------------
__device__ __forceinline__ uint32_t smem_u32(const void* p) {
    uint32_t a;
    asm("{ .reg .u64 t; cvta.to.shared.u64 t, %1; cvt.u32.u64 %0, t; }"
        : "=r"(a) : "l"(p));
    return a;
}
__device__ __forceinline__ void ldsm4(uint32_t& r0, uint32_t& r1,
                                      uint32_t& r2, uint32_t& r3, uint32_t a) {
    asm volatile("ldmatrix.sync.aligned.m8n8.x4.shared.b16 {%0,%1,%2,%3}, [%4];"
                 : "=r"(r0), "=r"(r1), "=r"(r2), "=r"(r3) : "r"(a));
}
__device__ __forceinline__ void mma_f16(float* d, const uint32_t* a,
                                        const uint32_t* b) {
    asm volatile(
        "mma.sync.aligned.m16n8k16.row.col.f32.f16.f16.f32 "
        "{%0,%1,%2,%3}, {%4,%5,%6,%7}, {%8,%9}, {%0,%1,%2,%3};"
        : "+f"(d[0]), "+f"(d[1]), "+f"(d[2]), "+f"(d[3])
        : "r"(a[0]), "r"(a[1]), "r"(a[2]), "r"(a[3]), "r"(b[0]), "r"(b[1]));
}
#define CP_ASYNC16(s, g) \
    asm volatile("cp.async.cg.shared.global [%0], [%1], 16;" :: "r"(s), "l"(g))
#define CP_COMMIT()  asm volatile("cp.async.commit_group;" ::: "memory")
#define CP_WAIT1()   asm volatile("cp.async.wait_group 1;" ::: "memory")

// ------------------------------ GEMM ---------------------------------------
// C[M,N] = A[M,K] @ B[N,K]^T (half in, fp16 MMA, fp32 acc). Row strides lda/ldb/ldc,
// per-z batch strides sA/sB/sC. 128x128 tile, BK=64, 3-stage cp.async,
// 4 warps (2x2), warp 64x64, 128 threads -> 2 CTAs/SM. (R9 core, unchanged)
static constexpr int BM = 128, BN = 128, BK = 64, STAGES = 3;
static constexpr int AB_BYTES    = BM * BK * 2;            // 16384
static constexpr int STAGE_BYTES = 2 * AB_BYTES;           // 32768
static constexpr int SMEM_TOTAL  = STAGES * STAGE_BYTES;   // 98304

__device__ __forceinline__ uint32_t swz(int r, int q) {
    return (uint32_t)(r * 128 + ((q ^ (r & 7)) << 4));
}

template <bool BIAS, bool SCALE, bool OUTH>
__global__ __launch_bounds__(128, 2) void tc_gemm(
    const __half* __restrict__ A, const __half* __restrict__ Bm,
    const float* __restrict__ bias, void* __restrict__ Cv,
    int M, int N, int K, int lda, int ldb, int ldc, float scale,
    long long sA, long long sB, long long sC)
{
    extern __shared__ __align__(1024) char smem[];
    const uint32_t sb = smem_u32(smem);

    const int tid  = threadIdx.x;
    const int lane = tid & 31;
    const int wid  = tid >> 5;          // 0..3
    const int wm   = (wid >> 1) * 64;   // 0 or 64
    const int wn   = (wid & 1) * 64;    // 0 or 64

    const long long bz = blockIdx.z;
    A  += bz * sA;
    Bm += bz * sB;
    const int m0 = blockIdx.y * BM;
    const int n0 = blockIdx.x * BN;
    const int nchunks = K / BK;

    const int midx = lane >> 3, l7 = lane & 7;
    int aR[4];
#pragma unroll
    for (int mi = 0; mi < 4; mi++) aR[mi] = wm + mi * 16 + ((midx & 1) << 3) + l7;
    const int aKH = midx >> 1;
    int bR[4];
#pragma unroll
    for (int n2 = 0; n2 < 4; n2++) bR[n2] = wn + n2 * 16 + ((midx >> 1) << 3) + l7;
    const int bKH = midx & 1;

    float acc[4][8][4];
#pragma unroll
    for (int mi = 0; mi < 4; mi++)
#pragma unroll
        for (int ni = 0; ni < 8; ni++)
#pragma unroll
            for (int j = 0; j < 4; j++) acc[mi][ni][j] = 0.0f;

    auto issue = [&](int c) {
        if (c < nchunks) {
            const int s = c % STAGES;
            const uint32_t As = sb + s * STAGE_BYTES;
            const uint32_t Bs = As + AB_BYTES;
            const int k0 = c * BK;
#pragma unroll
            for (int i = tid; i < 2048; i += 128) {
                const int idx = i & 1023;
                const int r = idx >> 3, q = idx & 7;
                if (i < 1024) {
                    CP_ASYNC16(As + swz(r, q),
                               A + (long long)(m0 + r) * lda + k0 + q * 8);
                } else {
                    CP_ASYNC16(Bs + swz(r, q),
                               Bm + (long long)(n0 + r) * ldb + k0 + q * 8);
                }
            }
        }
        CP_COMMIT();
    };

    issue(0);
    issue(1);

    for (int c = 0; c < nchunks; c++) {
        CP_WAIT1();
        __syncthreads();
        issue(c + 2);

        const int s = c % STAGES;
        const uint32_t As = sb + s * STAGE_BYTES;
        const uint32_t Bs = As + AB_BYTES;

#pragma unroll
        for (int kk = 0; kk < 4; kk++) {        // 4 x k16
            uint32_t aF[4][4], bF[8][2];
#pragma unroll
            for (int mi = 0; mi < 4; mi++)
                ldsm4(aF[mi][0], aF[mi][1], aF[mi][2], aF[mi][3],
                      As + swz(aR[mi], kk * 2 + aKH));
#pragma unroll
            for (int n2 = 0; n2 < 4; n2++) {
                uint32_t r0, r1, r2, r3;
                ldsm4(r0, r1, r2, r3, Bs + swz(bR[n2], kk * 2 + bKH));
                bF[n2 * 2 + 0][0] = r0;
                bF[n2 * 2 + 0][1] = r1;
                bF[n2 * 2 + 1][0] = r2;
                bF[n2 * 2 + 1][1] = r3;
            }
#pragma unroll
            for (int mi = 0; mi < 4; mi++)
#pragma unroll
                for (int ni = 0; ni < 8; ni++)
                    mma_f16(acc[mi][ni], aF[mi], bF[ni]);
        }
    }

    // ------------------ epilogue ------------------
    const int crow = lane >> 2;
    const int ccol = (lane & 3) * 2;
#pragma unroll
    for (int mi = 0; mi < 4; mi++) {
#pragma unroll
        for (int ni = 0; ni < 8; ni++) {
            const int col = n0 + wn + ni * 8 + ccol;
            float2 b2 = make_float2(0.f, 0.f);
            if (BIAS) b2 = *(const float2*)&bias[col];
#pragma unroll
            for (int h = 0; h < 2; h++) {
                const int row = m0 + wm + mi * 16 + crow + h * 8;
                float vx = acc[mi][ni][h * 2 + 0];
                float vy = acc[mi][ni][h * 2 + 1];
                if (SCALE) { vx *= scale; vy *= scale; }
                if (BIAS)  { vx += b2.x;  vy += b2.y; }
                if (OUTH) {
                    __half2* C = (__half2*)((__half*)Cv + bz * sC);
                    C[((long long)row * ldc + col) >> 1] = __floats2half2_rn(vx, vy);
                } else {
                    float* C = (float*)Cv + bz * sC;
                    *(float2*)&C[(long long)row * ldc + col] = make_float2(vx, vy);
                }
            }
        }
    }
}

// ------------------------------ prep (all conversions in one) --------------
static constexpr long long XG = 8192LL * 1024 / 4;      // float4 groups of x
static constexpr long long WG = 1024LL * 1024 / 4;      // per weight
static constexpr long long PREP_TOTAL = XG + 4 * WG + 768;

__global__ __launch_bounds__(256) void prep(
    const float* __restrict__ x,
    const float* __restrict__ Wq, const float* __restrict__ Wk,
    const float* __restrict__ Wv, const float* __restrict__ Wo,
    const float* __restrict__ bq, const float* __restrict__ bk,
    const float* __restrict__ bv,
    __half* __restrict__ xh, __half* __restrict__ Wcat,
    __half* __restrict__ Woh, float* __restrict__ bcat)
{
    const long long g = (long long)blockIdx.x * 256 + threadIdx.x;
    if (g >= PREP_TOTAL) return;

    const float* s;
    __half* d;
    long long off;
    if (g < XG)              { s = x;  d = xh;             off = g; }
    else if (g < XG + WG)    { s = Wq; d = Wcat;           off = g - XG; }
    else if (g < XG + 2*WG)  { s = Wk; d = Wcat + 1048576; off = g - XG - WG; }
    else if (g < XG + 3*WG)  { s = Wv; d = Wcat + 2097152; off = g - XG - 2*WG; }
    else if (g < XG + 4*WG)  { s = Wo; d = Woh;            off = g - XG - 3*WG; }
    else {
        const long long idx = (g - XG - 4*WG) * 4;      // 0..3068
        const float* bs = (idx < 1024) ? bq + idx
                        : (idx < 2048) ? bk + (idx - 1024)
                                       : bv + (idx - 2048);
        *(float4*)&bcat[idx] = *(const float4*)bs;
        return;
    }
    float4 v = *(const float4*)&s[off * 4];
    *(__half2*)&d[off * 4]     = __floats2half2_rn(v.x, v.y);
    *(__half2*)&d[off * 4 + 2] = __floats2half2_rn(v.z, v.w);
}

// ------------------------------ transpose (z = batch within pair) ----------
// dst[b][d][t] = src[b][t*3072 + d]
__global__ __launch_bounds__(256) void transpose_h(
    const __half* __restrict__ src, __half* __restrict__ dst)
{
    __shared__ __half tile[32][33];
    const long long b = blockIdx.z;
    src += b * 2048LL * 3072;
    dst += b * 2048LL * 1024;
    const int x0 = blockIdx.x * 32;   // d
    const int y0 = blockIdx.y * 32;   // t
    const int tx = threadIdx.x & 31;
    const int ty = threadIdx.x >> 5;
#pragma unroll
    for (int i = 0; i < 32; i += 8)
        tile[ty + i][tx] = src[(long long)(y0 + ty + i) * 3072 + x0 + tx];
    __syncthreads();
#pragma unroll
    for (int i = 0; i < 32; i += 8)
        dst[(long long)(x0 + ty + i) * 2048 + y0 + tx] = tile[tx][ty + i];
}

// ------------------------------ softmax (half, in place) -------------------
__global__ __launch_bounds__(256) void softmax_h(__half* __restrict__ S, int T)
{
    __shared__ float red[256];
    const long long row = blockIdx.x;
    __half* r = S + row * T;
    const int t = threadIdx.x;
    const int i = t * 8;                       // 8 halves per thread, T=2048

    uint4 u = *(const uint4*)&r[i];
    float v[8];
    {
        float2 f;
        f = __half22float2(*(__half2*)&u.x); v[0] = f.x; v[1] = f.y;
        f = __half22float2(*(__half2*)&u.y); v[2] = f.x; v[3] = f.y;
        f = __half22float2(*(__half2*)&u.z); v[4] = f.x; v[5] = f.y;
        f = __half22float2(*(__half2*)&u.w); v[6] = f.x; v[7] = f.y;
    }
    float m = v[0];
#pragma unroll
    for (int j = 1; j < 8; j++) m = fmaxf(m, v[j]);
    red[t] = m;
    __syncthreads();
    for (int s = 128; s > 0; s >>= 1) {
        if (t < s) red[t] = fmaxf(red[t], red[t + s]);
        __syncthreads();
    }
    m = red[0];
    __syncthreads();

    float sum = 0.0f;
#pragma unroll
    for (int j = 0; j < 8; j++) {
        v[j] = __expf(v[j] - m);
        sum += v[j];
    }
    red[t] = sum;
    __syncthreads();
    for (int s = 128; s > 0; s >>= 1) {
        if (t < s) red[t] += red[t + s];
        __syncthreads();
    }
    const float inv = 1.0f / red[0];

    uint4 o;
    *(__half2*)&o.x = __floats2half2_rn(v[0] * inv, v[1] * inv);
    *(__half2*)&o.y = __floats2half2_rn(v[2] * inv, v[3] * inv);
    *(__half2*)&o.z = __floats2half2_rn(v[4] * inv, v[5] * inv);
    *(__half2*)&o.w = __floats2half2_rn(v[6] * inv, v[7] * inv);
    *(uint4*)&r[i] = o;
}

// ------------------------------ launch -------------------------------------
extern "C" void kernel_launch(void* const* d_in, const int* in_sizes, int n_in,
                              void* d_out, int out_size)
{
    (void)in_sizes; (void)n_in; (void)out_size;
    const float* x  = (const float*)d_in[0];
    const float* Wq = (const float*)d_in[1];
    const float* bq = (const float*)d_in[2];
    const float* Wk = (const float*)d_in[3];
    const float* bk = (const float*)d_in[4];
    const float* Wv = (const float*)d_in[5];
    const float* bv = (const float*)d_in[6];
    const float* Wo = (const float*)d_in[7];
    const float* bo = (const float*)d_in[8];
    float* out = (float*)d_out;

    __half *xh, *Wcat, *Woh, *QKV, *Sh, *Vth, *Oh;
    float* bcat;
    cudaGetSymbolAddress((void**)&xh,   g_xh);
    cudaGetSymbolAddress((void**)&Wcat, g_Wcat);
    cudaGetSymbolAddress((void**)&Woh,  g_Woh);
    cudaGetSymbolAddress((void**)&bcat, g_bcat);
    cudaGetSymbolAddress((void**)&QKV,  g_QKV);
    cudaGetSymbolAddress((void**)&Sh,   g_Sh);
    cudaGetSymbolAddress((void**)&Vth,  g_Vth);
    cudaGetSymbolAddress((void**)&Oh,   g_Oh);

    const int T = 2048, D = 1024;
    const float scale = 0.03125f;   // 1/sqrt(1024)
    const long long sTT = (long long)T * T;
    const long long sTD = (long long)T * D;
    const long long sT3 = (long long)T * 3072;

    cudaFuncSetAttribute(tc_gemm<true,  false, true >,
                         cudaFuncAttributeMaxDynamicSharedMemorySize, SMEM_TOTAL);
    cudaFuncSetAttribute(tc_gemm<false, true,  true >,
                         cudaFuncAttributeMaxDynamicSharedMemorySize, SMEM_TOTAL);
    cudaFuncSetAttribute(tc_gemm<false, false, true >,
                         cudaFuncAttributeMaxDynamicSharedMemorySize, SMEM_TOTAL);
    cudaFuncSetAttribute(tc_gemm<true,  false, false>,
                         cudaFuncAttributeMaxDynamicSharedMemorySize, SMEM_TOTAL);

    // ONE extra stream + 2 events — the exact resource budget R7 proved safe.
    cudaStream_t s1;
    cudaStreamCreateWithFlags(&s1, cudaStreamNonBlocking);
    cudaEvent_t ePrep, eDone;
    cudaEventCreateWithFlags(&ePrep, cudaEventDisableTiming);
    cudaEventCreateWithFlags(&eDone, cudaEventDisableTiming);

    dim3 th(128);

    // 1) conversions + weight/bias concat on stream 0, fork to s1
    prep<<<(unsigned)((PREP_TOTAL + 255) / 256), 256>>>(
        x, Wq, Wk, Wv, Wo, bq, bk, bv, xh, Wcat, Woh, bcat);
    cudaEventRecord(ePrep, 0);
    cudaStreamWaitEvent(s1, ePrep, 0);

    // 2) two batch-pair chains: pair 0 = batches {0,1} on stream 0,
    //    pair 1 = batches {2,3} on s1. Each stage is ~half-machine-sized so
    //    the sibling chain fills its tail waves.
    for (int p = 0; p < 2; p++) {
        cudaStream_t s = (p == 0) ? (cudaStream_t)0 : s1;
        const long long b0 = 2 * p;
        const __half* xp   = xh  + b0 * sTD;
        __half*       qkvp = QKV + b0 * sT3;
        __half*       shp  = Sh  + b0 * sTT;
        __half*       vtp  = Vth + b0 * sTD;
        __half*       ohp  = Oh  + b0 * sTD;
        float*        outp = out + b0 * sTD;

        // QKV pair: [4096,3072] = xp @ Wcat^T + bcat        (768 CTAs)
        tc_gemm<true, false, true><<<dim3(3072 / BN, 2 * T / BM, 1), th, SMEM_TOTAL, s>>>(
            xp, Wcat, bcat, qkvp, 2 * T, 3072, D, D, D, 3072, 1.0f, 0, 0, 0);

        // Vt for both batches of the pair
        transpose_h<<<dim3(D / 32, T / 32, 2), 256, 0, s>>>(qkvp + 2048, vtp);

        // scores pair: Sh[b] = (Q K^T)/32                    (512 CTAs)
        tc_gemm<false, true, true><<<dim3(T / BN, T / BM, 2), th, SMEM_TOTAL, s>>>(
            qkvp, qkvp + 1024, nullptr, shp, T, T, D, 3072, 3072, T, scale,
            sT3, sT3, sTT);

        // softmax pair (4096 rows)
        softmax_h<<<2 * T, 256, 0, s>>>(shp, T);

        // PV pair: Oh[b] = P @ Vt^T                          (256 CTAs)
        tc_gemm<false, false, true><<<dim3(D / BN, T / BM, 2), th, SMEM_TOTAL, s>>>(
            shp, vtp, nullptr, ohp, T, D, T, T, T, D, 1.0f, sTT, sTD, sTD);

        // out pair: [4096,1024] = Oh @ Wo^T + bo             (256 CTAs)
        tc_gemm<true, false, false><<<dim3(D / BN, 2 * T / BM, 1), th, SMEM_TOTAL, s>>>(
            ohp, Woh, bo, outp, 2 * T, D, D, D, D, D, 1.0f, 0, 0, 0);
    }

    // join s1 back into stream 0
    cudaEventRecord(eDone, s1);
    cudaStreamWaitEvent(0, eDone, 0);
}

// round 12
// speedup vs baseline: 1.3998x; 1.1190x over previous
#include <cuda_runtime.h>
#include <cuda_fp16.h>
#include <cstdint>
#include <math.h>

// ------------------------------ scratch ------------------------------------
__device__ __half g_xh  [8192 * 1024];
__device__ __half g_Wcat[3 * 1024 * 1024];          // [Wq;Wk;Wv] as [3072,1024]
__device__ __half g_Woh [1024 * 1024];
__device__ float  g_bcat[3072];                     // [bq;bk;bv]
__device__ __half g_QKV [8192LL * 3072];            // per row: [Q|K|V]
__device__ __half g_Sh  [4LL * 2048 * 2048];        // scores -> softmax in place
__device__ __half g_Vth [8192 * 1024];              // V^T per batch [1024,2048]
__device__ __half g_Oh  [8192 * 1024];

// ------------------------------ helpers ------------------------------------
__device__ __forceinline__ uint32_t smem_u32(const void* p) {
    uint32_t a;
    asm("{ .reg .u64 t; cvta.to.shared.u64 t, %1; cvt.u32.u64 %0, t; }"
        : "=r"(a) : "l"(p));
    return a;
}
__device__ __forceinline__ void ldsm4(uint32_t& r0, uint32_t& r1,
                                      uint32_t& r2, uint32_t& r3, uint32_t a) {
    asm volatile("ldmatrix.sync.aligned.m8n8.x4.shared.b16 {%0,%1,%2,%3}, [%4];"
                 : "=r"(r0), "=r"(r1), "=r"(r2), "=r"(r3) : "r"(a));
}
__device__ __forceinline__ void mma_f16(float* d, const uint32_t* a,
                                        const uint32_t* b) {
    asm volatile(
        "mma.sync.aligned.m16n8k16.row.col.f32.f16.f16.f32 "
        "{%0,%1,%2,%3}, {%4,%5,%6,%7}, {%8,%9}, {%0,%1,%2,%3};"
        : "+f"(d[0]), "+f"(d[1]), "+f"(d[2]), "+f"(d[3])
        : "r"(a[0]), "r"(a[1]), "r"(a[2]), "r"(a[3]), "r"(b[0]), "r"(b[1]));
}
#define CP_ASYNC16(s, g) \
    asm volatile("cp.async.cg.shared.global [%0], [%1], 16;" :: "r"(s), "l"(g))
#define CP_COMMIT()  asm volatile("cp.async.commit_group;" ::: "memory")
#define CP_WAIT2()   asm volatile("cp.async.wait_group 2;" ::: "memory")

// ------------------------------ GEMM ---------------------------------------
// C[M,N] = A[M,K] @ B[N,K]^T (half in, fp16 MMA, fp32 acc). Row strides lda/ldb/ldc,
// per-z batch strides sA/sB/sC.
// 128x128 tile, BK=32, SIX 16KB cp.async stages, 4 warps (2x2) of 64x64,
// 128 threads -> 2 CTAs/SM.  Fragment double-buffering + cross-chunk prefetch:
// wait_group(2)+sync publishes stage c+2, so chunk c prefetches (c+1, kk=0)
// BEFORE the barrier -> MMAs never wait on a fresh LDSM after a sync.
static constexpr int BM = 128, BN = 128, BK = 32, STAGES = 6;
static constexpr int A_BYTES     = BM * BK * 2;            // 8192
static constexpr int STAGE_BYTES = 2 * A_BYTES;            // 16384
static constexpr int SMEM_TOTAL  = STAGES * STAGE_BYTES;   // 98304

// swizzle for 64-byte rows (4x16B quads): off = r*64 + ((q ^ ((r>>1)&3))<<4)
// -> the 8 rows of any ldmatrix octet land in 8 distinct 16B columns.
struct Frag { uint32_t a[4][4]; uint32_t b[8][2]; };

template <bool BIAS, bool SCALE, bool OUTH>
__global__ __launch_bounds__(128, 2) void tc_gemm(
    const __half* __restrict__ A, const __half* __restrict__ Bm,
    const float* __restrict__ bias, void* __restrict__ Cv,
    int M, int N, int K, int lda, int ldb, int ldc, float scale,
    long long sA, long long sB, long long sC)
{
    extern __shared__ __align__(1024) char smem[];
    const uint32_t sb = smem_u32(smem);
    const uint32_t sbEnd = sb + STAGES * STAGE_BYTES;

    const int tid  = threadIdx.x;
    const int lane = tid & 31;
    const int wid  = tid >> 5;          // 0..3
    const int wm   = (wid >> 1) * 64;
    const int wn   = (wid & 1) * 64;

    const long long bz = blockIdx.z;
    A  += bz * sA;
    Bm += bz * sB;
    const int m0 = blockIdx.y * BM;
    const int n0 = blockIdx.x * BN;
    const int nchunks = K / BK;

    // ldmatrix source rows + swizzle row components
    const int midx = lane >> 3, l7 = lane & 7;
    const int aQ = midx >> 1;           // 0/1 : k16-half within quad pair
    const int bQ = midx & 1;
    uint32_t aOff[4], aX[4], bOff[4], bX[4];
#pragma unroll
    for (int mi = 0; mi < 4; mi++) {
        int r = wm + mi * 16 + ((midx & 1) << 3) + l7;
        aOff[mi] = (uint32_t)r * 64;
        aX[mi]   = (uint32_t)(((r >> 1) & 3) << 4);
    }
#pragma unroll
    for (int n2 = 0; n2 < 4; n2++) {
        int r = wn + n2 * 16 + ((midx >> 1) << 3) + l7;
        bOff[n2] = (uint32_t)r * 64;
        bX[n2]   = (uint32_t)(((r >> 1) & 3) << 4);
    }

    float acc[4][8][4];
#pragma unroll
    for (int mi = 0; mi < 4; mi++)
#pragma unroll
        for (int ni = 0; ni < 8; ni++)
#pragma unroll
            for (int j = 0; j < 4; j++) acc[mi][ni][j] = 0.0f;

    // ---- producer state: monotonically advancing write stage + k offset ----
    uint32_t wSt = sb;
    int wK = 0;
    const __half* aP = A + (long long)m0 * lda;
    const __half* bP = Bm + (long long)n0 * ldb;
    auto issue = [&]() {
        if (wK < K) {
#pragma unroll
            for (int i = tid; i < 1024; i += 128) {
                const int idx = i & 511;
                const int r = idx >> 2, q = idx & 3;
                const uint32_t soff =
                    (uint32_t)r * 64 + (uint32_t)((q ^ ((r >> 1) & 3)) << 4);
                if (i < 512)
                    CP_ASYNC16(wSt + soff, aP + (long long)r * lda + wK + q * 8);
                else
                    CP_ASYNC16(wSt + A_BYTES + soff,
                               bP + (long long)r * ldb + wK + q * 8);
            }
        }
        CP_COMMIT();
        wK += BK;
        wSt += STAGE_BYTES;
        if (wSt == sbEnd) wSt = sb;
    };

    auto ldfrag = [&](Frag& f, uint32_t st, int kk) {
        const uint32_t qa = (uint32_t)((kk * 2 + aQ) << 4);
        const uint32_t qb = (uint32_t)((kk * 2 + bQ) << 4);
#pragma unroll
        for (int mi = 0; mi < 4; mi++)
            ldsm4(f.a[mi][0], f.a[mi][1], f.a[mi][2], f.a[mi][3],
                  st + aOff[mi] + (qa ^ aX[mi]));
#pragma unroll
        for (int n2 = 0; n2 < 4; n2++) {
            uint32_t r0, r1, r2, r3;
            ldsm4(r0, r1, r2, r3, st + A_BYTES + bOff[n2] + (qb ^ bX[n2]));
            f.b[2 * n2 + 0][0] = r0;
            f.b[2 * n2 + 0][1] = r1;
            f.b[2 * n2 + 1][0] = r2;
            f.b[2 * n2 + 1][1] = r3;
        }
    };
    auto mmall = [&](Frag& f) {
#pragma unroll
        for (int mi = 0; mi < 4; mi++)
#pragma unroll
            for (int ni = 0; ni < 8; ni++)
                mma_f16(acc[mi][ni], f.a[mi], f.b[ni]);
    };

    // ---- prologue: 4 chunks in flight; chunks 0,1 complete + published ----
    issue(); issue(); issue(); issue();
    CP_WAIT2();
    __syncthreads();

    Frag f0, f1;
    uint32_t rSt = sb;                 // read stage of current chunk
    ldfrag(f0, rSt, 0);

    for (int c = 0; c < nchunks; c++) {
        ldfrag(f1, rSt, 1);            // (c, kk=1)
        mmall(f0);
        const uint32_t rNext =
            (c + 1 < nchunks)
                ? (rSt + STAGE_BYTES == sbEnd ? sb : rSt + STAGE_BYTES)
                : rSt;
        ldfrag(f0, rNext, 0);          // (c+1, kk=0) — published (<= c+2 done)
        mmall(f1);
        rSt = rNext;
        issue();                       // chunk c+4 (stage (c+4)%6, readers done)
        CP_WAIT2();                    // chunks <= c+2 complete
        __syncthreads();               // ... and published to all warps
    }

    // ------------------ epilogue ------------------
    const int crow = lane >> 2;
    const int ccol = (lane & 3) * 2;
#pragma unroll
    for (int mi = 0; mi < 4; mi++) {
#pragma unroll
        for (int ni = 0; ni < 8; ni++) {
            const int col = n0 + wn + ni * 8 + ccol;
            float2 b2 = make_float2(0.f, 0.f);
            if (BIAS) b2 = *(const float2*)&bias[col];
#pragma unroll
            for (int h = 0; h < 2; h++) {
                const int row = m0 + wm + mi * 16 + crow + h * 8;
                float vx = acc[mi][ni][h * 2 + 0];
                float vy = acc[mi][ni][h * 2 + 1];
                if (SCALE) { vx *= scale; vy *= scale; }
                if (BIAS)  { vx += b2.x;  vy += b2.y; }
                if (OUTH) {
                    __half2* C = (__half2*)((__half*)Cv + bz * sC);
                    C[((long long)row * ldc + col) >> 1] = __floats2half2_rn(vx, vy);
                } else {
                    float* C = (float*)Cv + bz * sC;
                    *(float2*)&C[(long long)row * ldc + col] = make_float2(vx, vy);
                }
            }
        }
    }
}

// ------------------------------ prep (all conversions in one) --------------
static constexpr long long XG = 8192LL * 1024 / 4;      // float4 groups of x
static constexpr long long WG = 1024LL * 1024 / 4;      // per weight
static constexpr long long PREP_TOTAL = XG + 4 * WG + 768;

__global__ __launch_bounds__(256) void prep(
    const float* __restrict__ x,
    const float* __restrict__ Wq, const float* __restrict__ Wk,
    const float* __restrict__ Wv, const float* __restrict__ Wo,
    const float* __restrict__ bq, const float* __restrict__ bk,
    const float* __restrict__ bv,
    __half* __restrict__ xh, __half* __restrict__ Wcat,
    __half* __restrict__ Woh, float* __restrict__ bcat)
{
    const long long g = (long long)blockIdx.x * 256 + threadIdx.x;
    if (g >= PREP_TOTAL) return;

    const float* s;
    __half* d;
    long long off;
    if (g < XG)              { s = x;  d = xh;             off = g; }
    else if (g < XG + WG)    { s = Wq; d = Wcat;           off = g - XG; }
    else if (g < XG + 2*WG)  { s = Wk; d = Wcat + 1048576; off = g - XG - WG; }
    else if (g < XG + 3*WG)  { s = Wv; d = Wcat + 2097152; off = g - XG - 2*WG; }
    else if (g < XG + 4*WG)  { s = Wo; d = Woh;            off = g - XG - 3*WG; }
    else {
        const long long idx = (g - XG - 4*WG) * 4;      // 0..3068
        const float* bs = (idx < 1024) ? bq + idx
                        : (idx < 2048) ? bk + (idx - 1024)
                                       : bv + (idx - 2048);
        *(float4*)&bcat[idx] = *(const float4*)bs;
        return;
    }
    float4 v = *(const float4*)&s[off * 4];
    *(__half2*)&d[off * 4]     = __floats2half2_rn(v.x, v.y);
    *(__half2*)&d[off * 4 + 2] = __floats2half2_rn(v.z, v.w);
}

// ------------------------------ transpose (z = batch within pair) ----------
__global__ __launch_bounds__(256) void transpose_h(
    const __half* __restrict__ src, __half* __restrict__ dst)
{
    __shared__ __half tile[32][33];
    const long long b = blockIdx.z;
    src += b * 2048LL * 3072;
    dst += b * 2048LL * 1024;
    const int x0 = blockIdx.x * 32;   // d
    const int y0 = blockIdx.y * 32;   // t
    const int tx = threadIdx.x & 31;
    const int ty = threadIdx.x >> 5;
#pragma unroll
    for (int i = 0; i < 32; i += 8)
        tile[ty + i][tx] = src[(long long)(y0 + ty + i) * 3072 + x0 + tx];
    __syncthreads();
#pragma unroll
    for (int i = 0; i < 32; i += 8)
        dst[(long long)(x0 + ty + i) * 2048 + y0 + tx] = tile[tx][ty + i];
}

// ------------------------------ softmax (half, in place) -------------------
__global__ __launch_bounds__(256) void softmax_h(__half* __restrict__ S, int T)
{
    __shared__ float red[256];
    const long long row = blockIdx.x;
    __half* r = S + row * T;
    const int t = threadIdx.x;
    const int i = t * 8;                       // 8 halves per thread, T=2048

    uint4 u = *(const uint4*)&r[i];
    float v[8];
    {
        float2 f;
        f = __half22float2(*(__half2*)&u.x); v[0] = f.x; v[1] = f.y;
        f = __half22float2(*(__half2*)&u.y); v[2] = f.x; v[3] = f.y;
        f = __half22float2(*(__half2*)&u.z); v[4] = f.x; v[5] = f.y;
        f = __half22float2(*(__half2*)&u.w); v[6] = f.x; v[7] = f.y;
    }
    float m = v[0];
#pragma unroll
    for (int j = 1; j < 8; j++) m = fmaxf(m, v[j]);
    red[t] = m;
    __syncthreads();
    for (int s = 128; s > 0; s >>= 1) {
        if (t < s) red[t] = fmaxf(red[t], red[t + s]);
        __syncthreads();
    }
    m = red[0];
    __syncthreads();

    float sum = 0.0f;
#pragma unroll
    for (int j = 0; j < 8; j++) {
        v[j] = __expf(v[j] - m);
        sum += v[j];
    }
    red[t] = sum;
    __syncthreads();
    for (int s = 128; s > 0; s >>= 1) {
        if (t < s) red[t] += red[t + s];
        __syncthreads();
    }
    const float inv = 1.0f / red[0];

    uint4 o;
    *(__half2*)&o.x = __floats2half2_rn(v[0] * inv, v[1] * inv);
    *(__half2*)&o.y = __floats2half2_rn(v[2] * inv, v[3] * inv);
    *(__half2*)&o.z = __floats2half2_rn(v[4] * inv, v[5] * inv);
    *(__half2*)&o.w = __floats2half2_rn(v[6] * inv, v[7] * inv);
    *(uint4*)&r[i] = o;
}

// ------------------------------ launch -------------------------------------
extern "C" void kernel_launch(void* const* d_in, const int* in_sizes, int n_in,
                              void* d_out, int out_size)
{
    (void)in_sizes; (void)n_in; (void)out_size;
    const float* x  = (const float*)d_in[0];
    const float* Wq = (const float*)d_in[1];
    const float* bq = (const float*)d_in[2];
    const float* Wk = (const float*)d_in[3];
    const float* bk = (const float*)d_in[4];
    const float* Wv = (const float*)d_in[5];
    const float* bv = (const float*)d_in[6];
    const float* Wo = (const float*)d_in[7];
    const float* bo = (const float*)d_in[8];
    float* out = (float*)d_out;

    __half *xh, *Wcat, *Woh, *QKV, *Sh, *Vth, *Oh;
    float* bcat;
    cudaGetSymbolAddress((void**)&xh,   g_xh);
    cudaGetSymbolAddress((void**)&Wcat, g_Wcat);
    cudaGetSymbolAddress((void**)&Woh,  g_Woh);
    cudaGetSymbolAddress((void**)&bcat, g_bcat);
    cudaGetSymbolAddress((void**)&QKV,  g_QKV);
    cudaGetSymbolAddress((void**)&Sh,   g_Sh);
    cudaGetSymbolAddress((void**)&Vth,  g_Vth);
    cudaGetSymbolAddress((void**)&Oh,   g_Oh);

    const int T = 2048, D = 1024;
    const float scale = 0.03125f;   // 1/sqrt(1024)
    const long long sTT = (long long)T * T;
    const long long sTD = (long long)T * D;
    const long long sT3 = (long long)T * 3072;

    cudaFuncSetAttribute(tc_gemm<true,  false, true >,
                         cudaFuncAttributeMaxDynamicSharedMemorySize, SMEM_TOTAL);
    cudaFuncSetAttribute(tc_gemm<false, true,  true >,
                         cudaFuncAttributeMaxDynamicSharedMemorySize, SMEM_TOTAL);
    cudaFuncSetAttribute(tc_gemm<false, false, true >,
                         cudaFuncAttributeMaxDynamicSharedMemorySize, SMEM_TOTAL);
    cudaFuncSetAttribute(tc_gemm<true,  false, false>,
                         cudaFuncAttributeMaxDynamicSharedMemorySize, SMEM_TOTAL);

    // ONE extra stream + 2 events — R7/R11-proven resource budget.
    cudaStream_t s1;
    cudaStreamCreateWithFlags(&s1, cudaStreamNonBlocking);
    cudaEvent_t ePrep, eDone;
    cudaEventCreateWithFlags(&ePrep, cudaEventDisableTiming);
    cudaEventCreateWithFlags(&eDone, cudaEventDisableTiming);

    dim3 th(128);

    // 1) conversions + weight/bias concat on stream 0, fork to s1
    prep<<<(unsigned)((PREP_TOTAL + 255) / 256), 256>>>(
        x, Wq, Wk, Wv, Wo, bq, bk, bv, xh, Wcat, Woh, bcat);
    cudaEventRecord(ePrep, 0);
    cudaStreamWaitEvent(s1, ePrep, 0);

    // 2) two batch-pair chains: batches {0,1} on stream 0, {2,3} on s1.
    for (int p = 0; p < 2; p++) {
        cudaStream_t s = (p == 0) ? (cudaStream_t)0 : s1;
        const long long b0 = 2 * p;
        const __half* xp   = xh  + b0 * sTD;
        __half*       qkvp = QKV + b0 * sT3;
        __half*       shp  = Sh  + b0 * sTT;
        __half*       vtp  = Vth + b0 * sTD;
        __half*       ohp  = Oh  + b0 * sTD;
        float*        outp = out + b0 * sTD;

        // QKV pair: [4096,3072] = xp @ Wcat^T + bcat        (768 CTAs)
        tc_gemm<true, false, true><<<dim3(3072 / BN, 2 * T / BM, 1), th, SMEM_TOTAL, s>>>(
            xp, Wcat, bcat, qkvp, 2 * T, 3072, D, D, D, 3072, 1.0f, 0, 0, 0);

        // Vt for both batches of the pair
        transpose_h<<<dim3(D / 32, T / 32, 2), 256, 0, s>>>(qkvp + 2048, vtp);

        // scores pair: Sh[b] = (Q K^T)/32                    (512 CTAs)
        tc_gemm<false, true, true><<<dim3(T / BN, T / BM, 2), th, SMEM_TOTAL, s>>>(
            qkvp, qkvp + 1024, nullptr, shp, T, T, D, 3072, 3072, T, scale,
            sT3, sT3, sTT);

        // softmax pair (4096 rows)
        softmax_h<<<2 * T, 256, 0, s>>>(shp, T);

        // PV pair: Oh[b] = P @ Vt^T                          (256 CTAs)
        tc_gemm<false, false, true><<<dim3(D / BN, T / BM, 2), th, SMEM_TOTAL, s>>>(
            shp, vtp, nullptr, ohp, T, D, T, T, T, D, 1.0f, sTT, sTD, sTD);

        // out pair: [4096,1024] = Oh @ Wo^T + bo             (256 CTAs)
        tc_gemm<true, false, false><<<dim3(D / BN, 2 * T / BM, 1), th, SMEM_TOTAL, s>>>(
            ohp, Woh, bo, outp, 2 * T, D, D, D, D, D, 1.0f, 0, 0, 0);
    }

    // join s1 back into stream 0
    cudaEventRecord(eDone, s1);
    cudaStreamWaitEvent(0, eDone, 0);
}